// round 2
// baseline (speedup 1.0000x reference)
#include <cuda_runtime.h>
#include <cstdint>

#define CC       256
#define HWC      3136
#define NBATCH   32
#define MM       (NBATCH*HWC)   /* 100352 */
#define MT       128
#define NTILES   (MM/MT)        /* 784 */
#define KC       32
#define NCH      (CC/KC)        /* 8 */
#define NTHREADS 512
#define SMEM_BYTES (2*KC*MT*4 + 2*KC*CC*4 + MT*4)  /* 98816 */

// -------------------- device scratch --------------------
__device__ float    g_buf[(size_t)CC*MM];
__device__ float    ut_buf[CC*CC];
__device__ float    chsum_d[CC];
__device__ unsigned gmax_d[CC];
__device__ unsigned gmin_d[CC];
__device__ float    mn_d[CC], s_d[CC], dmin_d[CC], scale_d[CC], inv_d[CC], cvv_d[CC];
__device__ float    qsum_d[CC], bias_d[CC];
__device__ int      same_d[CC];

// -------------------- helpers --------------------
__device__ __forceinline__ unsigned long long pk(float lo, float hi) {
    unsigned long long r;
    asm("mov.b64 %0, {%1,%2};" : "=l"(r) : "f"(lo), "f"(hi));
    return r;
}
__device__ __forceinline__ unsigned long long pk2(float v) { return pk(v, v); }
__device__ __forceinline__ void fma2(unsigned long long& d, unsigned long long a, unsigned long long b) {
    asm("fma.rn.f32x2 %0, %1, %2, %0;" : "+l"(d) : "l"(a), "l"(b));
}
__device__ __forceinline__ void upk(unsigned long long v, float& lo, float& hi) {
    asm("mov.b64 {%0,%1}, %2;" : "=f"(lo), "=f"(hi) : "l"(v));
}
__device__ __forceinline__ void cp16(void* s, const void* g) {
    unsigned sa = (unsigned)__cvta_generic_to_shared(s);
    asm volatile("cp.async.ca.shared.global [%0], [%1], 16;" :: "r"(sa), "l"(g) : "memory");
}
__device__ __forceinline__ void cp_commit() { asm volatile("cp.async.commit_group;" ::: "memory"); }
__device__ __forceinline__ void cp_wait1()  { asm volatile("cp.async.wait_group 1;" ::: "memory"); }
__device__ __forceinline__ void cp_wait0()  { asm volatile("cp.async.wait_group 0;" ::: "memory"); }

// order-preserving float<->uint for atomic max/min
__device__ __forceinline__ unsigned encf(float f) {
    unsigned u = __float_as_uint(f);
    return (u & 0x80000000u) ? ~u : (u | 0x80000000u);
}
__device__ __forceinline__ float decf(unsigned u) {
    unsigned b = (u & 0x80000000u) ? (u & 0x7FFFFFFFu) : ~u;
    return __uint_as_float(b);
}

// -------------------- init --------------------
__global__ void init_k(const float* __restrict__ u) {
    int t = threadIdx.x, b = blockIdx.x;
    if (b == 0) {
        chsum_d[t] = 0.0f; qsum_d[t] = 0.0f;
        gmax_d[t] = 0u;  gmin_d[t] = 0xFFFFFFFFu;
    } else {
        int j = b - 1;
        ut_buf[(size_t)j*CC + t] = u[(size_t)t*CC + j];
    }
}

// -------------------- GEMM (MODE 0: g = u^T relu(x); MODE 1: out = u q + bias) ----
template<int MODE>
__global__ void __launch_bounds__(NTHREADS, 1)
gemm_k(const float* __restrict__ xin, const float* __restrict__ uin, float* __restrict__ og)
{
    extern __shared__ char smem_raw[];
    float* im_s = (float*)smem_raw;                              // [2][KC][MT]
    float* u_s  = (float*)(smem_raw + 2*KC*MT*4);                // [2][KC][CC]
    int*   coff = (int*)  (smem_raw + 2*KC*MT*4 + 2*KC*CC*4);    // [MT]

    const int tid = threadIdx.x;
    const int m0  = blockIdx.x * MT;
    const float* A = MODE ? (const float*)g_buf : xin;
    const float* B = MODE ? (const float*)ut_buf : uin;

    if (tid < MT) {
        int m = m0 + tid;
        int n = m / HWC;
        coff[tid] = n * (CC*HWC) + (m - n*HWC);
    }
    __syncthreads();

    auto stage = [&](int buf, int kc) {
        const int bk = kc * KC;
        float* imd = im_s + buf*(KC*MT);
        float* ud  = u_s  + buf*(KC*CC);
        #pragma unroll
        for (int i = 0; i < 2; i++) {            // 1024 16B units
            int uix = tid + i*NTHREADS;
            int r   = uix >> 5;
            int s4  = (uix & 31) << 2;
            const float* src;
            if (MODE) src = A + (size_t)(bk + r)*MM + (m0 + s4);
            else      src = A + (size_t)coff[s4] + (size_t)(bk + r)*HWC;
            cp16(imd + r*MT + s4, src);
        }
        #pragma unroll
        for (int i = 0; i < 4; i++) {            // 2048 16B units
            int uix = tid + i*NTHREADS;
            int r   = uix >> 6;
            int s4  = (uix & 63) << 2;
            cp16(ud + r*CC + s4, B + (size_t)(bk + r)*CC + s4);
        }
    };

    unsigned long long acc[8][4] = {};   // 8 j x 8 m, packed f32x2
    const int tx = tid & 15;             // m-group
    const int ty = tid >> 4;             // j-group

    stage(0, 0); cp_commit();

    for (int kc = 0; kc < NCH; kc++) {
        const int buf = kc & 1;
        if (kc + 1 < NCH) { stage(buf ^ 1, kc + 1); cp_commit(); cp_wait1(); }
        else              { cp_wait0(); }
        __syncthreads();

        const float* imb = im_s + buf*(KC*MT);
        const float* ub  = u_s  + buf*(KC*CC);

        if (!MODE) {
            // fused channel sums of relu(x)
            int r = tid >> 4;
            const float4* pp = (const float4*)(imb + r*MT + ((tid & 15) << 3));
            float4 v0 = pp[0], v1 = pp[1];
            float sl = fmaxf(v0.x,0.f)+fmaxf(v0.y,0.f)+fmaxf(v0.z,0.f)+fmaxf(v0.w,0.f)
                     + fmaxf(v1.x,0.f)+fmaxf(v1.y,0.f)+fmaxf(v1.z,0.f)+fmaxf(v1.w,0.f);
            sl += __shfl_xor_sync(0xffffffffu, sl, 1);
            sl += __shfl_xor_sync(0xffffffffu, sl, 2);
            sl += __shfl_xor_sync(0xffffffffu, sl, 4);
            sl += __shfl_xor_sync(0xffffffffu, sl, 8);
            if ((tid & 15) == 0) atomicAdd(&chsum_d[kc*KC + r], sl);
        }

        #pragma unroll 8
        for (int k = 0; k < KC; k++) {
            float4 a0 = *(const float4*)(imb + k*MT + tx*8);
            float4 a1 = *(const float4*)(imb + k*MT + tx*8 + 4);
            if (!MODE) {
                a0.x = fmaxf(a0.x, 0.f); a0.y = fmaxf(a0.y, 0.f);
                a0.z = fmaxf(a0.z, 0.f); a0.w = fmaxf(a0.w, 0.f);
                a1.x = fmaxf(a1.x, 0.f); a1.y = fmaxf(a1.y, 0.f);
                a1.z = fmaxf(a1.z, 0.f); a1.w = fmaxf(a1.w, 0.f);
            }
            float4 b0 = *(const float4*)(ub + k*CC + ty*8);
            float4 b1 = *(const float4*)(ub + k*CC + ty*8 + 4);
            unsigned long long Av[4] = { pk(a0.x,a0.y), pk(a0.z,a0.w), pk(a1.x,a1.y), pk(a1.z,a1.w) };
            unsigned long long Bv[8] = { pk2(b0.x), pk2(b0.y), pk2(b0.z), pk2(b0.w),
                                         pk2(b1.x), pk2(b1.y), pk2(b1.z), pk2(b1.w) };
            #pragma unroll
            for (int jj = 0; jj < 8; jj++)
                #pragma unroll
                for (int mm = 0; mm < 4; mm++)
                    fma2(acc[jj][mm], Bv[jj], Av[mm]);
        }
        __syncthreads();
    }

    if (!MODE) {
        #pragma unroll
        for (int jj = 0; jj < 8; jj++) {
            int j = ty*8 + jj;
            float v[8];
            upk(acc[jj][0], v[0], v[1]); upk(acc[jj][1], v[2], v[3]);
            upk(acc[jj][2], v[4], v[5]); upk(acc[jj][3], v[6], v[7]);
            float* dst = g_buf + (size_t)j*MM + m0 + tx*8;
            ((float4*)dst)[0] = make_float4(v[0], v[1], v[2], v[3]);
            ((float4*)dst)[1] = make_float4(v[4], v[5], v[6], v[7]);
            float mx = v[0], mnv = v[0];
            #pragma unroll
            for (int t = 1; t < 8; t++) { mx = fmaxf(mx, v[t]); mnv = fminf(mnv, v[t]); }
            #pragma unroll
            for (int d = 1; d < 16; d <<= 1) {
                mx  = fmaxf(mx,  __shfl_xor_sync(0xffffffffu, mx,  d));
                mnv = fminf(mnv, __shfl_xor_sync(0xffffffffu, mnv, d));
            }
            if (tx == 0) {
                atomicMax(&gmax_d[j], encf(mx));
                atomicMin(&gmin_d[j], encf(mnv));
            }
        }
    } else {
        int cb = coff[tx*8];   // 8-m group never crosses image boundary (3136 % 8 == 0)
        #pragma unroll
        for (int jj = 0; jj < 8; jj++) {
            int c = ty*8 + jj;
            float bb = bias_d[c];
            float v[8];
            upk(acc[jj][0], v[0], v[1]); upk(acc[jj][1], v[2], v[3]);
            upk(acc[jj][2], v[4], v[5]); upk(acc[jj][3], v[6], v[7]);
            float* dst = og + (size_t)cb + (size_t)c*HWC;
            ((float4*)dst)[0] = make_float4(v[0]+bb, v[1]+bb, v[2]+bb, v[3]+bb);
            ((float4*)dst)[1] = make_float4(v[4]+bb, v[5]+bb, v[6]+bb, v[7]+bb);
        }
    }
}

// -------------------- mid: mn, s, dmin/scale per row --------------------
__global__ void mid_k(const float* __restrict__ u, const float* __restrict__ cv,
                      const int* __restrict__ abw) {
    __shared__ float mns[CC];
    int t = threadIdx.x;
    float mn = chsum_d[t] * (1.0f / (float)MM);
    mn_d[t] = mn; mns[t] = mn;
    __syncthreads();
    float s = 0.0f;
    #pragma unroll 8
    for (int c = 0; c < CC; c++) s += u[(size_t)c*CC + t] * mns[c];
    s_d[t] = s;
    float c = cv[t]; cvv_d[t] = c;
    int ab = abw ? *abw : 8;
    float dmax = fminf(fmaxf(decf(gmax_d[t]) - s, -c), c);
    float dmin = fminf(fmaxf(decf(gmin_d[t]) - s, -c), c);
    int same = (dmax == dmin) || (ab >= 17);
    float rng = same ? 1.0f : (dmax - dmin);
    float levels = (float)((1 << (same ? 8 : ab)) - 1);
    same_d[t]  = same;
    dmin_d[t]  = dmin;
    scale_d[t] = levels / rng;
    inv_d[t]   = rng / levels;
}

// -------------------- quantize (in-place on g_buf) --------------------
__global__ void __launch_bounds__(512, 2) quant_k() {
    __shared__ float red[16];
    int j = blockIdx.y;
    size_t base = (size_t)j*MM + (size_t)blockIdx.x*2048 + threadIdx.x*4;
    float s = s_d[j], dmin = dmin_d[j], sc = scale_d[j], inv = inv_d[j], cv = cvv_d[j];
    int same = same_d[j];
    float4 v = *(float4*)(g_buf + base);
    float q[4] = {v.x, v.y, v.z, v.w};
    float sum = 0.0f;
    #pragma unroll
    for (int i = 0; i < 4; i++) {
        float val = fminf(fmaxf(q[i] - s, -cv), cv);
        float qq  = rintf((val - dmin) * sc) * inv + dmin;
        q[i] = same ? val : qq;
        sum += q[i];
    }
    *(float4*)(g_buf + base) = make_float4(q[0], q[1], q[2], q[3]);
    #pragma unroll
    for (int d = 1; d < 32; d <<= 1) sum += __shfl_xor_sync(0xffffffffu, sum, d);
    int lane = threadIdx.x & 31, wid = threadIdx.x >> 5;
    if (lane == 0) red[wid] = sum;
    __syncthreads();
    if (threadIdx.x < 16) {
        float r = red[threadIdx.x];
        #pragma unroll
        for (int d = 1; d < 16; d <<= 1) r += __shfl_xor_sync(0xffffu, r, d);
        if (threadIdx.x == 0) atomicAdd(&qsum_d[j], r);
    }
}

// -------------------- bias --------------------
__global__ void bias_k(const float* __restrict__ u) {
    __shared__ float qm[CC];
    int t = threadIdx.x;
    qm[t] = qsum_d[t] * (1.0f / (float)MM);
    __syncthreads();
    float b = 0.0f;
    #pragma unroll 8
    for (int j = 0; j < CC; j++) b += u[(size_t)t*CC + j] * qm[j];
    bias_d[t] = mn_d[t] - b;
}

// -------------------- launcher --------------------
extern "C" void kernel_launch(void* const* d_in, const int* in_sizes, int n_in,
                              void* d_out, int out_size) {
    const float* x  = (const float*)d_in[0];
    const float* u  = (const float*)d_in[1];
    const float* cv = (const float*)d_in[2];
    const int*   ab = (n_in > 3) ? (const int*)d_in[3] : nullptr;
    float* out = (float*)d_out;
    (void)in_sizes; (void)out_size;

    cudaFuncSetAttribute(gemm_k<0>, cudaFuncAttributeMaxDynamicSharedMemorySize, SMEM_BYTES);
    cudaFuncSetAttribute(gemm_k<1>, cudaFuncAttributeMaxDynamicSharedMemorySize, SMEM_BYTES);

    init_k<<<CC + 1, CC>>>(u);
    gemm_k<0><<<NTILES, NTHREADS, SMEM_BYTES>>>(x, u, nullptr);
    mid_k<<<1, CC>>>(u, cv, ab);
    quant_k<<<dim3(MM/2048, CC), 512>>>();
    bias_k<<<1, CC>>>(u);
    gemm_k<1><<<NTILES, NTHREADS, SMEM_BYTES>>>(nullptr, nullptr, out);
}